// round 13
// baseline (speedup 1.0000x reference)
#include <cuda_runtime.h>

// SSIM loss, fused single pass. (u,v)=(p+t,p-t) rotation, f32x2 packed.
// NT=256, 2 cols/thread, 9 strips -> grid 432 -> ~3 CTAs/SM -> ~6 warps/SMSP.
// __launch_bounds__(256,3): 85-reg budget. Slide-form window (min live regs).
// 2 rows per barrier (4 row buffers), 2-row LDG prefetch.
// UV ring in registers (static slots); Q ring in smem. 1 rcp per 2 cols.
// Last-block finalize. pred/target: (16,3,512,512) fp32 -> out: 16 fp32.

#define WIDTH   512
#define HEIGHT  512
#define PADR    5
#define NT      256
#define NSTRIP  9
#define STRIPH  57
#define RS2     528
#define NBLOCKS (48 * NSTRIP)

// smem byte offsets (dynamic)
#define OF_Q    0              // 11*256*16 = 45056
#define OF_ROW  45056          // 4*528*8   = 16896
#define OF_RED  61952          // 256*4
#define SMEM_SZ 62976

// SSIM constants with 1/121 folded out: K1=C1*121^2, K2=C2*121^2
#define K1f 1.4641f
#define K2f 13.1769f

typedef unsigned long long u64;

__device__ float g_partials[NBLOCKS];
__device__ unsigned int g_count;

__device__ __forceinline__ u64 pk2(float a, float b) {
    u64 r; asm("mov.b64 %0,{%1,%2};" : "=l"(r) : "f"(a), "f"(b)); return r;
}
__device__ __forceinline__ float2 up2(u64 a) {
    float2 r; asm("mov.b64 {%0,%1},%2;" : "=f"(r.x), "=f"(r.y) : "l"(a)); return r;
}
__device__ __forceinline__ u64 add2(u64 a, u64 b) {
    u64 r; asm("add.rn.f32x2 %0,%1,%2;" : "=l"(r) : "l"(a), "l"(b)); return r;
}
__device__ __forceinline__ u64 mul2(u64 a, u64 b) {
    u64 r; asm("mul.rn.f32x2 %0,%1,%2;" : "=l"(r) : "l"(a), "l"(b)); return r;
}
__device__ __forceinline__ u64 fma2(u64 a, u64 b, u64 c) {
    u64 r; asm("fma.rn.f32x2 %0,%1,%2,%3;" : "=l"(r) : "l"(a), "l"(b), "l"(c)); return r;
}
__device__ __forceinline__ float rcpa(float x) {
    float r; asm("rcp.approx.f32 %0,%1;" : "=f"(r) : "f"(x)); return r;
}

// Horizontal 11-tap windows for 2 output columns (x0, x0+1), slide form.
// Taps from buffer idx [x0+3, x0+14]; loads LDS.64 + 5x LDS.128 + LDS.64.
// Slide form keeps few taps live -> low register pressure.
__device__ __forceinline__ void hwin2(const float2* __restrict__ row, int x0,
                                      u64 M1, u64 hUV[2], u64 hQ[2])
{
    u64 T0 = *(const u64*)(row + x0 + 3);
    ulonglong2 A = *(const ulonglong2*)(row + x0 + 4);
    ulonglong2 B = *(const ulonglong2*)(row + x0 + 6);
    ulonglong2 C = *(const ulonglong2*)(row + x0 + 8);
    ulonglong2 D = *(const ulonglong2*)(row + x0 + 10);
    ulonglong2 E = *(const ulonglong2*)(row + x0 + 12);
    u64 T11 = *(const u64*)(row + x0 + 14);

    u64 s = T0;
    u64 q = mul2(T0, T0);
    s = add2(s, A.x); q = fma2(A.x, A.x, q);
    s = add2(s, A.y); q = fma2(A.y, A.y, q);
    s = add2(s, B.x); q = fma2(B.x, B.x, q);
    s = add2(s, B.y); q = fma2(B.y, B.y, q);
    s = add2(s, C.x); q = fma2(C.x, C.x, q);
    s = add2(s, C.y); q = fma2(C.y, C.y, q);
    s = add2(s, D.x); q = fma2(D.x, D.x, q);
    s = add2(s, D.y); q = fma2(D.y, D.y, q);
    s = add2(s, E.x); q = fma2(E.x, E.x, q);
    s = add2(s, E.y); q = fma2(E.y, E.y, q);
    hUV[0] = s; hQ[0] = q;
    // slide by one: +T11, -T0
    s = add2(s, T11);
    s = fma2(T0, M1, s);
    q = fma2(T11, T11, q);
    q = fma2(T0, mul2(T0, M1), q);
    hUV[1] = s; hQ[1] = q;
}

// SSIM emit for 2 columns; one rcp serves both divides.
__device__ __forceinline__ void emit2(const u64 SUV[2], const u64 SQ2[2], float& acc)
{
    float n[2], d[2];
#pragma unroll
    for (int c = 0; c < 2; c++) {
        float2 qf = up2(SQ2[c]);                 // (Qu, Qv)
        float2 s2 = up2(mul2(SUV[c], SUV[c]));   // (Su^2, Sv^2)
        float A = s2.x - s2.y;                   // 4*Mx*My
        float B = s2.x + s2.y;                   // 2*(Mx^2+My^2)
        float qd = qf.x - qf.y;                  // 4*S(pt)
        float qs = qf.x + qf.y;                  // 2*(Sp2+St2)
        float a  = fmaf(0.5f, A, K1f);
        float b  = fmaf(60.5f, qd, fmaf(-0.5f, A, K2f));
        n[c] = a * b;
        float d1 = fmaf(0.5f, B, K1f);
        float d2 = fmaf(60.5f, qs, fmaf(-0.5f, B, K2f));
        d[c] = d1 * d2;
    }
    float r = rcpa(d[0] * d[1]);
    acc += __saturatef(n[0] * r * d[1]) + __saturatef(n[1] * r * d[0]);
}

__global__ __launch_bounds__(NT, 3)
void ssim_main_kernel(const float* __restrict__ pred, const float* __restrict__ targ,
                      float* __restrict__ out)
{
    extern __shared__ char sm[];
    float2* rowbuf = (float2*)(sm + OF_ROW);   // 4 buffers of RS2 (u,v) packed
    float*  red    = (float*)(sm + OF_RED);
    __shared__ int s_last;

    const int tid   = threadIdx.x;
    const int bid   = blockIdx.x;
    const int img   = bid / NSTRIP;
    const int strip = bid - img * NSTRIP;
    const int r0    = strip * STRIPH;
    const int r1    = min(HEIGHT, r0 + STRIPH);
    const int yend  = r1 + PADR;
    const int emit0 = r0 + PADR;
    const int start = r0 - PADR;

    const float* __restrict__ P = pred + (size_t)img * (WIDTH * HEIGHT);
    const float* __restrict__ T = targ + (size_t)img * (WIDTH * HEIGHT);
    const int x0 = tid * 2;

    const u64 M1 = pk2(-1.f, -1.f);

    // UV ring in registers (static slots via full unroll below)
    u64 rUV[11][2];
#pragma unroll
    for (int s = 0; s < 11; s++) { rUV[s][0] = 0; rUV[s][1] = 0; }

    // Q ring in smem (per-thread slots, compile-time offsets)
    ulonglong2* qring = (ulonglong2*)(sm + OF_Q) + tid;
    {
        ulonglong2 z2 = make_ulonglong2(0ull, 0ull);
#pragma unroll
        for (int s = 0; s < 11; s++) qring[s * NT] = z2;
    }
    // zero pads of 4 row buffers: idx 3..7 (x=-5..-1) and 520..524 (x=512..516)
    if (tid < 40) {
        int r = tid / 10, k = tid % 10;
        int idx = (k < 5) ? (3 + k) : (520 + (k - 5));
        rowbuf[r * RS2 + idx] = make_float2(0.f, 0.f);
    }

    u64 SUV[2] = {0, 0}, SQ2[2] = {0, 0};
    float acc = 0.f;

    // prefetch rows start, start+1
    float2 cp0 = {}, ct0 = {}, cp1 = {}, ct1 = {};
    if (start >= 0) {
        cp0 = *(const float2*)(P + (size_t)start * WIDTH + x0);
        ct0 = *(const float2*)(T + (size_t)start * WIDTH + x0);
    }
    if (start + 1 >= 0) {
        cp1 = *(const float2*)(P + (size_t)(start + 1) * WIDTH + x0);
        ct1 = *(const float2*)(T + (size_t)(start + 1) * WIDTH + x0);
    }

    __syncthreads();   // pads + zeroed ring visible

    int kpar = 0;
    for (int y0 = start; y0 < yend; y0 += 22, kpar ^= 1) {
#pragma unroll
        for (int p = 0; p < 11; p++) {
            const int base = y0 + 2 * p;
            if (base < yend) {                      // uniform across block
                const int pb = kpar ^ (p & 1);
                float2* rA = rowbuf + (pb * 2 + 0) * RS2;
                float2* rB = rowbuf + (pb * 2 + 1) * RS2;
                const bool vA = (base >= 0) && (base < HEIGHT);
                const bool vB = (base + 1 >= 0) && (base + 1 < HEIGHT);

                // write 2 rows (zeros for invalid -> branch-free compute)
                {
                    float4 w = make_float4(0.f, 0.f, 0.f, 0.f);
                    if (vA)
                        w = make_float4(cp0.x + ct0.x, cp0.x - ct0.x,
                                        cp0.y + ct0.y, cp0.y - ct0.y);
                    *(float4*)(rA + x0 + 8) = w;
                    w = make_float4(0.f, 0.f, 0.f, 0.f);
                    if (vB)
                        w = make_float4(cp1.x + ct1.x, cp1.x - ct1.x,
                                        cp1.y + ct1.y, cp1.y - ct1.y);
                    *(float4*)(rB + x0 + 8) = w;
                }
                // prefetch next row pair
                {
                    int yn0 = base + 2, yn1 = base + 3;
                    if (yn0 >= 0 && yn0 < HEIGHT) {
                        cp0 = *(const float2*)(P + (size_t)yn0 * WIDTH + x0);
                        ct0 = *(const float2*)(T + (size_t)yn0 * WIDTH + x0);
                    }
                    if (yn1 >= 0 && yn1 < HEIGHT) {
                        cp1 = *(const float2*)(P + (size_t)yn1 * WIDTH + x0);
                        ct1 = *(const float2*)(T + (size_t)yn1 * WIDTH + x0);
                    }
                }
                __syncthreads();   // row pair visible (alternating pair-buffers)

                u64 hUV[2], hQ[2];
                // ---- row A, ring slot (2p)%11 (compile-time constant) ----
                hwin2(rA, x0, M1, hUV, hQ);
                {
                    const int sA = (2 * p) % 11;
                    ulonglong2 q = qring[sA * NT];
                    SUV[0] = add2(SUV[0], fma2(rUV[sA][0], M1, hUV[0]));
                    SUV[1] = add2(SUV[1], fma2(rUV[sA][1], M1, hUV[1]));
                    SQ2[0] = add2(SQ2[0], fma2(q.x, M1, hQ[0]));
                    SQ2[1] = add2(SQ2[1], fma2(q.y, M1, hQ[1]));
                    rUV[sA][0] = hUV[0]; rUV[sA][1] = hUV[1];
                    qring[sA * NT] = make_ulonglong2(hQ[0], hQ[1]);
                }
                if (base >= emit0) emit2(SUV, SQ2, acc);

                // ---- row B, ring slot (2p+1)%11 ----
                hwin2(rB, x0, M1, hUV, hQ);
                {
                    const int sB = (2 * p + 1) % 11;
                    ulonglong2 q = qring[sB * NT];
                    SUV[0] = add2(SUV[0], fma2(rUV[sB][0], M1, hUV[0]));
                    SUV[1] = add2(SUV[1], fma2(rUV[sB][1], M1, hUV[1]));
                    SQ2[0] = add2(SQ2[0], fma2(q.x, M1, hQ[0]));
                    SQ2[1] = add2(SQ2[1], fma2(q.y, M1, hQ[1]));
                    rUV[sB][0] = hUV[0]; rUV[sB][1] = hUV[1];
                    qring[sB * NT] = make_ulonglong2(hQ[0], hQ[1]);
                }
                if (base + 1 >= emit0 && base + 1 < yend) emit2(SUV, SQ2, acc);
            }
        }
    }

    // deterministic block reduction
    red[tid] = acc;
    __syncthreads();
#pragma unroll
    for (int s = NT / 2; s > 0; s >>= 1) {
        if (tid < s) red[tid] += red[tid + s];
        __syncthreads();
    }
    if (tid == 0) {
        g_partials[bid] = red[0];
        __threadfence();
        unsigned int c = atomicAdd(&g_count, 1);
        s_last = (c == NBLOCKS - 1);
    }
    __syncthreads();
    if (s_last) {
        if (tid < 16) {
            float s = 0.f;
#pragma unroll
            for (int j = 0; j < 3 * NSTRIP; j++)
                s += __ldcg(&g_partials[tid * (3 * NSTRIP) + j]);
            out[tid] = 1.f - s * (1.f / (3.f * 512.f * 512.f));
        }
        if (tid == 0) g_count = 0;   // reset for next graph replay
    }
}

extern "C" void kernel_launch(void* const* d_in, const int* in_sizes, int n_in,
                              void* d_out, int out_size) {
    const float* pred = (const float*)d_in[0];
    const float* targ = (const float*)d_in[1];
    cudaFuncSetAttribute(ssim_main_kernel,
                         cudaFuncAttributeMaxDynamicSharedMemorySize, SMEM_SZ);
    ssim_main_kernel<<<NBLOCKS, NT, SMEM_SZ>>>(pred, targ, (float*)d_out);
}

// round 14
// speedup vs baseline: 1.0491x; 1.0491x over previous
#include <cuda_runtime.h>

// SSIM loss, fused single pass. (u,v)=(p+t,p-t) rotation, f32x2 packed.
// Tree-structured horizontal windows; ALL window loads conflict-free LDS.128.
// NT=256, 2 cols/thread, 6 strips -> grid 288 -> 2 CTAs/SM -> 4 warps/SMSP.
// 2 rows per barrier (4 row buffers), 2-row LDG prefetch.
// UV ring in registers (static slots); Q ring in smem. 1 rcp per 2 cols.
// Last-block finalize. pred/target: (16,3,512,512) fp32 -> out: 16 fp32.

#define WIDTH   512
#define HEIGHT  512
#define PADR    5
#define NT      256
#define NSTRIP  6
#define STRIPH  86
#define RS2     528
#define NBLOCKS (48 * NSTRIP)

// smem byte offsets (dynamic)
#define OF_Q    0              // 11*256*16 = 45056
#define OF_ROW  45056          // 4*528*8   = 16896
#define OF_RED  61952          // 256*4
#define SMEM_SZ 62976

// SSIM constants with 1/121 folded out: K1=C1*121^2, K2=C2*121^2
#define K1f 1.4641f
#define K2f 13.1769f

typedef unsigned long long u64;

__device__ float g_partials[NBLOCKS];
__device__ unsigned int g_count;

__device__ __forceinline__ u64 pk2(float a, float b) {
    u64 r; asm("mov.b64 %0,{%1,%2};" : "=l"(r) : "f"(a), "f"(b)); return r;
}
__device__ __forceinline__ float2 up2(u64 a) {
    float2 r; asm("mov.b64 {%0,%1},%2;" : "=f"(r.x), "=f"(r.y) : "l"(a)); return r;
}
__device__ __forceinline__ u64 add2(u64 a, u64 b) {
    u64 r; asm("add.rn.f32x2 %0,%1,%2;" : "=l"(r) : "l"(a), "l"(b)); return r;
}
__device__ __forceinline__ u64 mul2(u64 a, u64 b) {
    u64 r; asm("mul.rn.f32x2 %0,%1,%2;" : "=l"(r) : "l"(a), "l"(b)); return r;
}
__device__ __forceinline__ u64 fma2(u64 a, u64 b, u64 c) {
    u64 r; asm("fma.rn.f32x2 %0,%1,%2,%3;" : "=l"(r) : "l"(a), "l"(b), "l"(c)); return r;
}
__device__ __forceinline__ float rcpa(float x) {
    float r; asm("rcp.approx.f32 %0,%1;" : "=f"(r) : "f"(x)); return r;
}

// Horizontal 11-tap windows for 2 output columns (x0, x0+1), tree-structured.
// Window col x0:   buffer idx [x0+3, x0+13]
// Window col x0+1: buffer idx [x0+4, x0+14]
// own0/own1 = idx x0+8, x0+9 kept in regs.
// ALL smem loads are 16B-aligned LDS.128 at 16B thread stride -> conflict-free.
// Edge taps come from padded LDS.128s ([x0+2,x0+3] and [x0+14,x0+15]).
__device__ __forceinline__ void hwin2(const float2* __restrict__ row, int x0,
                                      u64 own0, u64 own1,
                                      u64 hUV[2], u64 hQ[2])
{
    ulonglong2 L0 = *(const ulonglong2*)(row + x0 + 2);    // idx x0+2 (dead), x0+3
    ulonglong2 L1 = *(const ulonglong2*)(row + x0 + 4);    // x0+4, x0+5
    ulonglong2 L2 = *(const ulonglong2*)(row + x0 + 6);    // x0+6, x0+7
    ulonglong2 L3 = *(const ulonglong2*)(row + x0 + 10);   // x0+10, x0+11
    ulonglong2 L4 = *(const ulonglong2*)(row + x0 + 12);   // x0+12, x0+13
    ulonglong2 L5 = *(const ulonglong2*)(row + x0 + 14);   // x0+14, x0+15 (dead)
    const u64 T0  = L0.y;
    const u64 T11 = L5.x;

    // sum chains (independent; combine depth ~6)
    u64 c1 = add2(add2(L1.x, L1.y), add2(L2.x, L2.y));
    c1 = add2(c1, own0);
    u64 c2 = add2(add2(own1, L3.x), add2(L3.y, L4.x));
    c2 = add2(c2, L4.y);
    u64 mid = add2(c1, c2);
    hUV[0] = add2(mid, T0);
    hUV[1] = add2(mid, T11);

    // square-sum chains (two independent fma chains)
    u64 q1 = fma2(L1.y, L1.y, mul2(L1.x, L1.x));
    q1 = fma2(L2.x, L2.x, q1);
    q1 = fma2(L2.y, L2.y, q1);
    q1 = fma2(own0, own0, q1);
    u64 q2 = fma2(L3.x, L3.x, mul2(own1, own1));
    q2 = fma2(L3.y, L3.y, q2);
    q2 = fma2(L4.x, L4.x, q2);
    q2 = fma2(L4.y, L4.y, q2);
    u64 midq = add2(q1, q2);
    hQ[0] = fma2(T0, T0, midq);
    hQ[1] = fma2(T11, T11, midq);
}

// SSIM emit for 2 columns; one rcp serves both divides.
__device__ __forceinline__ void emit2(const u64 SUV[2], const u64 SQ2[2], float& acc)
{
    float n[2], d[2];
#pragma unroll
    for (int c = 0; c < 2; c++) {
        float2 qf = up2(SQ2[c]);                 // (Qu, Qv)
        float2 s2 = up2(mul2(SUV[c], SUV[c]));   // (Su^2, Sv^2)
        float A = s2.x - s2.y;                   // 4*Mx*My
        float B = s2.x + s2.y;                   // 2*(Mx^2+My^2)
        float qd = qf.x - qf.y;                  // 4*S(pt)
        float qs = qf.x + qf.y;                  // 2*(Sp2+St2)
        float a  = fmaf(0.5f, A, K1f);
        float b  = fmaf(60.5f, qd, fmaf(-0.5f, A, K2f));
        n[c] = a * b;
        float d1 = fmaf(0.5f, B, K1f);
        float d2 = fmaf(60.5f, qs, fmaf(-0.5f, B, K2f));
        d[c] = d1 * d2;
    }
    float r = rcpa(d[0] * d[1]);
    acc += __saturatef(n[0] * r * d[1]) + __saturatef(n[1] * r * d[0]);
}

__global__ __launch_bounds__(NT, 2)
void ssim_main_kernel(const float* __restrict__ pred, const float* __restrict__ targ,
                      float* __restrict__ out)
{
    extern __shared__ char sm[];
    float2* rowbuf = (float2*)(sm + OF_ROW);   // 4 buffers of RS2 (u,v) packed
    float*  red    = (float*)(sm + OF_RED);
    __shared__ int s_last;

    const int tid   = threadIdx.x;
    const int bid   = blockIdx.x;
    const int img   = bid / NSTRIP;
    const int strip = bid - img * NSTRIP;
    const int r0    = strip * STRIPH;
    const int r1    = min(HEIGHT, r0 + STRIPH);
    const int yend  = r1 + PADR;
    const int emit0 = r0 + PADR;
    const int start = r0 - PADR;

    const float* __restrict__ P = pred + (size_t)img * (WIDTH * HEIGHT);
    const float* __restrict__ T = targ + (size_t)img * (WIDTH * HEIGHT);
    const int x0 = tid * 2;

    const u64 M1 = pk2(-1.f, -1.f);

    // UV ring in registers (static slots via full unroll below)
    u64 rUV[11][2];
#pragma unroll
    for (int s = 0; s < 11; s++) { rUV[s][0] = 0; rUV[s][1] = 0; }

    // Q ring in smem (per-thread slots, compile-time offsets)
    ulonglong2* qring = (ulonglong2*)(sm + OF_Q) + tid;
    {
        ulonglong2 z2 = make_ulonglong2(0ull, 0ull);
#pragma unroll
        for (int s = 0; s < 11; s++) qring[s * NT] = z2;
    }
    // zero pads of 4 row buffers: idx 2..7 (x=-6..-1) and 520..525 (x=512..517)
    // (one extra pad on each side for the padded edge LDS.128s)
    if (tid < 48) {
        int r = tid / 12, k = tid % 12;
        int idx = (k < 6) ? (2 + k) : (520 + (k - 6));
        rowbuf[r * RS2 + idx] = make_float2(0.f, 0.f);
    }

    u64 SUV[2] = {0, 0}, SQ2[2] = {0, 0};
    float acc = 0.f;

    // prefetch rows start, start+1
    float2 cp0 = {}, ct0 = {}, cp1 = {}, ct1 = {};
    if (start >= 0) {
        cp0 = *(const float2*)(P + (size_t)start * WIDTH + x0);
        ct0 = *(const float2*)(T + (size_t)start * WIDTH + x0);
    }
    if (start + 1 >= 0) {
        cp1 = *(const float2*)(P + (size_t)(start + 1) * WIDTH + x0);
        ct1 = *(const float2*)(T + (size_t)(start + 1) * WIDTH + x0);
    }

    __syncthreads();   // pads + zeroed ring visible

    int kpar = 0;
    for (int y0 = start; y0 < yend; y0 += 22, kpar ^= 1) {
#pragma unroll
        for (int p = 0; p < 11; p++) {
            const int base = y0 + 2 * p;
            if (base < yend) {                      // uniform across block
                const int pb = kpar ^ (p & 1);
                float2* rA = rowbuf + (pb * 2 + 0) * RS2;
                float2* rB = rowbuf + (pb * 2 + 1) * RS2;
                const bool vA = (base >= 0) && (base < HEIGHT);
                const bool vB = (base + 1 >= 0) && (base + 1 < HEIGHT);

                u64 oA0 = 0, oA1 = 0, oB0 = 0, oB1 = 0;
                if (vA) {
                    float u0 = cp0.x + ct0.x, v0 = cp0.x - ct0.x;
                    float u1 = cp0.y + ct0.y, v1 = cp0.y - ct0.y;
                    oA0 = pk2(u0, v0); oA1 = pk2(u1, v1);
                    *(float4*)(rA + x0 + 8) = make_float4(u0, v0, u1, v1);
                } else {
                    *(float4*)(rA + x0 + 8) = make_float4(0.f, 0.f, 0.f, 0.f);
                }
                if (vB) {
                    float u0 = cp1.x + ct1.x, v0 = cp1.x - ct1.x;
                    float u1 = cp1.y + ct1.y, v1 = cp1.y - ct1.y;
                    oB0 = pk2(u0, v0); oB1 = pk2(u1, v1);
                    *(float4*)(rB + x0 + 8) = make_float4(u0, v0, u1, v1);
                } else {
                    *(float4*)(rB + x0 + 8) = make_float4(0.f, 0.f, 0.f, 0.f);
                }
                // prefetch next row pair
                {
                    int yn0 = base + 2, yn1 = base + 3;
                    if (yn0 >= 0 && yn0 < HEIGHT) {
                        cp0 = *(const float2*)(P + (size_t)yn0 * WIDTH + x0);
                        ct0 = *(const float2*)(T + (size_t)yn0 * WIDTH + x0);
                    }
                    if (yn1 >= 0 && yn1 < HEIGHT) {
                        cp1 = *(const float2*)(P + (size_t)yn1 * WIDTH + x0);
                        ct1 = *(const float2*)(T + (size_t)yn1 * WIDTH + x0);
                    }
                }
                __syncthreads();   // row pair visible (alternating pair-buffers)

                u64 hUV[2], hQ[2];
                // ---- row A, ring slot (2p)%11 (compile-time constant) ----
                hwin2(rA, x0, oA0, oA1, hUV, hQ);
                {
                    const int sA = (2 * p) % 11;
                    ulonglong2 q = qring[sA * NT];
                    SUV[0] = add2(SUV[0], fma2(rUV[sA][0], M1, hUV[0]));
                    SUV[1] = add2(SUV[1], fma2(rUV[sA][1], M1, hUV[1]));
                    SQ2[0] = add2(SQ2[0], fma2(q.x, M1, hQ[0]));
                    SQ2[1] = add2(SQ2[1], fma2(q.y, M1, hQ[1]));
                    rUV[sA][0] = hUV[0]; rUV[sA][1] = hUV[1];
                    qring[sA * NT] = make_ulonglong2(hQ[0], hQ[1]);
                }
                if (base >= emit0) emit2(SUV, SQ2, acc);

                // ---- row B, ring slot (2p+1)%11 ----
                hwin2(rB, x0, oB0, oB1, hUV, hQ);
                {
                    const int sB = (2 * p + 1) % 11;
                    ulonglong2 q = qring[sB * NT];
                    SUV[0] = add2(SUV[0], fma2(rUV[sB][0], M1, hUV[0]));
                    SUV[1] = add2(SUV[1], fma2(rUV[sB][1], M1, hUV[1]));
                    SQ2[0] = add2(SQ2[0], fma2(q.x, M1, hQ[0]));
                    SQ2[1] = add2(SQ2[1], fma2(q.y, M1, hQ[1]));
                    rUV[sB][0] = hUV[0]; rUV[sB][1] = hUV[1];
                    qring[sB * NT] = make_ulonglong2(hQ[0], hQ[1]);
                }
                if (base + 1 >= emit0 && base + 1 < yend) emit2(SUV, SQ2, acc);
            }
        }
    }

    // deterministic block reduction
    red[tid] = acc;
    __syncthreads();
#pragma unroll
    for (int s = NT / 2; s > 0; s >>= 1) {
        if (tid < s) red[tid] += red[tid + s];
        __syncthreads();
    }
    if (tid == 0) {
        g_partials[bid] = red[0];
        __threadfence();
        unsigned int c = atomicAdd(&g_count, 1);
        s_last = (c == NBLOCKS - 1);
    }
    __syncthreads();
    if (s_last) {
        if (tid < 16) {
            float s = 0.f;
#pragma unroll
            for (int j = 0; j < 3 * NSTRIP; j++)
                s += __ldcg(&g_partials[tid * (3 * NSTRIP) + j]);
            out[tid] = 1.f - s * (1.f / (3.f * 512.f * 512.f));
        }
        if (tid == 0) g_count = 0;   // reset for next graph replay
    }
}

extern "C" void kernel_launch(void* const* d_in, const int* in_sizes, int n_in,
                              void* d_out, int out_size) {
    const float* pred = (const float*)d_in[0];
    const float* targ = (const float*)d_in[1];
    cudaFuncSetAttribute(ssim_main_kernel,
                         cudaFuncAttributeMaxDynamicSharedMemorySize, SMEM_SZ);
    ssim_main_kernel<<<NBLOCKS, NT, SMEM_SZ>>>(pred, targ, (float*)d_out);
}

// round 16
// speedup vs baseline: 1.0583x; 1.0088x over previous
#include <cuda_runtime.h>

// SSIM loss, fused single pass. (u,v)=(p+t,p-t) rotation, f32x2 packed.
// WARP-PRIVATE row tiles (64 cols + 6-col halos, redundant halo LDG):
// mainloop has NO __syncthreads -- only __syncwarp. Warps fully decoupled.
// NT=256, 2 cols/thread, 6 strips -> grid 288 -> 2 CTAs/SM -> 4 warps/SMSP.
// UV ring in registers (static slots); Q ring in smem (thread-private).
// 1 rcp per 2 cols. Last-block finalize.
// pred/target: (16,3,512,512) fp32 -> out: 16 fp32 (1 - mean ssim per sample).

#define WIDTH   512
#define HEIGHT  512
#define PADR    5
#define NT      256
#define NSTRIP  6
#define STRIPH  86
#define WRS     80             // float2 slots per warp-row-buffer
#define NBLOCKS (48 * NSTRIP)

// smem byte offsets (dynamic)
#define OF_Q    0              // 11*256*16 = 45056
#define OF_ROW  45056          // 4 sets * 8 warps * 80 * 8 = 20480
#define OF_RED  65536          // 256*4
#define SMEM_SZ 66560

// SSIM constants with 1/121 folded out: K1=C1*121^2, K2=C2*121^2
#define K1f 1.4641f
#define K2f 13.1769f

typedef unsigned long long u64;

__device__ float g_partials[NBLOCKS];
__device__ unsigned int g_count;

__device__ __forceinline__ u64 pk2(float a, float b) {
    u64 r; asm("mov.b64 %0,{%1,%2};" : "=l"(r) : "f"(a), "f"(b)); return r;
}
__device__ __forceinline__ float2 up2(u64 a) {
    float2 r; asm("mov.b64 {%0,%1},%2;" : "=f"(r.x), "=f"(r.y) : "l"(a)); return r;
}
__device__ __forceinline__ u64 add2(u64 a, u64 b) {
    u64 r; asm("add.rn.f32x2 %0,%1,%2;" : "=l"(r) : "l"(a), "l"(b)); return r;
}
__device__ __forceinline__ u64 mul2(u64 a, u64 b) {
    u64 r; asm("mul.rn.f32x2 %0,%1,%2;" : "=l"(r) : "l"(a), "l"(b)); return r;
}
__device__ __forceinline__ u64 fma2(u64 a, u64 b, u64 c) {
    u64 r; asm("fma.rn.f32x2 %0,%1,%2,%3;" : "=l"(r) : "l"(a), "l"(b), "l"(c)); return r;
}
__device__ __forceinline__ float rcpa(float x) {
    float r; asm("rcp.approx.f32 %0,%1;" : "=f"(r) : "f"(x)); return r;
}

// Horizontal 11-tap windows for 2 output cols, tree-structured.
// Buffer-local col base xb=2*lane; taps at buffer idx [xb+3, xb+14];
// own0/own1 = idx xb+8, xb+9 kept in regs.
__device__ __forceinline__ void hwin2(const float2* __restrict__ row, int xb,
                                      u64 own0, u64 own1,
                                      u64 hUV[2], u64 hQ[2])
{
    ulonglong2 L0 = *(const ulonglong2*)(row + xb + 2);    // xb+2 (dead), xb+3
    ulonglong2 L1 = *(const ulonglong2*)(row + xb + 4);
    ulonglong2 L2 = *(const ulonglong2*)(row + xb + 6);
    ulonglong2 L3 = *(const ulonglong2*)(row + xb + 10);
    ulonglong2 L4 = *(const ulonglong2*)(row + xb + 12);
    ulonglong2 L5 = *(const ulonglong2*)(row + xb + 14);   // xb+14, xb+15 (dead)
    const u64 T0  = L0.y;
    const u64 T11 = L5.x;

    u64 c1 = add2(add2(L1.x, L1.y), add2(L2.x, L2.y));
    c1 = add2(c1, own0);
    u64 c2 = add2(add2(own1, L3.x), add2(L3.y, L4.x));
    c2 = add2(c2, L4.y);
    u64 mid = add2(c1, c2);
    hUV[0] = add2(mid, T0);
    hUV[1] = add2(mid, T11);

    u64 q1 = fma2(L1.y, L1.y, mul2(L1.x, L1.x));
    q1 = fma2(L2.x, L2.x, q1);
    q1 = fma2(L2.y, L2.y, q1);
    q1 = fma2(own0, own0, q1);
    u64 q2 = fma2(L3.x, L3.x, mul2(own1, own1));
    q2 = fma2(L3.y, L3.y, q2);
    q2 = fma2(L4.x, L4.x, q2);
    q2 = fma2(L4.y, L4.y, q2);
    u64 midq = add2(q1, q2);
    hQ[0] = fma2(T0, T0, midq);
    hQ[1] = fma2(T11, T11, midq);
}

// SSIM emit for 2 columns; one rcp serves both divides.
__device__ __forceinline__ void emit2(const u64 SUV[2], const u64 SQ2[2], float& acc)
{
    float n[2], d[2];
#pragma unroll
    for (int c = 0; c < 2; c++) {
        float2 qf = up2(SQ2[c]);                 // (Qu, Qv)
        float2 s2 = up2(mul2(SUV[c], SUV[c]));   // (Su^2, Sv^2)
        float A = s2.x - s2.y;                   // 4*Mx*My
        float B = s2.x + s2.y;                   // 2*(Mx^2+My^2)
        float qd = qf.x - qf.y;                  // 4*S(pt)
        float qs = qf.x + qf.y;                  // 2*(Sp2+St2)
        float a  = fmaf(0.5f, A, K1f);
        float b  = fmaf(60.5f, qd, fmaf(-0.5f, A, K2f));
        n[c] = a * b;
        float d1 = fmaf(0.5f, B, K1f);
        float d2 = fmaf(60.5f, qs, fmaf(-0.5f, B, K2f));
        d[c] = d1 * d2;
    }
    float r = rcpa(d[0] * d[1]);
    acc += __saturatef(n[0] * r * d[1]) + __saturatef(n[1] * r * d[0]);
}

__global__ __launch_bounds__(NT, 2)
void ssim_main_kernel(const float* __restrict__ pred, const float* __restrict__ targ,
                      float* __restrict__ out)
{
    extern __shared__ char sm[];
    float2* rowbuf = (float2*)(sm + OF_ROW);   // [4 sets][8 warps][WRS]
    float*  red    = (float*)(sm + OF_RED);
    __shared__ int s_last;

    const int tid   = threadIdx.x;
    const int w     = tid >> 5;
    const int l     = tid & 31;
    const int bid   = blockIdx.x;
    const int img   = bid / NSTRIP;
    const int strip = bid - img * NSTRIP;
    const int r0    = strip * STRIPH;
    const int r1    = min(HEIGHT, r0 + STRIPH);
    const int yend  = r1 + PADR;
    const int emit0 = r0 + PADR;
    const int start = r0 - PADR;

    const float* __restrict__ P = pred + (size_t)img * (WIDTH * HEIGHT);
    const float* __restrict__ T = targ + (size_t)img * (WIDTH * HEIGHT);
    const int x0g = 64 * w + 2 * l;   // global col of own pair
    const int xb  = 2 * l;            // buffer-local col base (+8 offset for data)

    // halo duty for lanes 0..5 (2 cols each, float2-aligned)
    const int  hcol = (l < 3) ? (64 * w - 6 + 2 * l) : (64 * w + 64 + 2 * (l - 3));
    const int  hbuf = (l < 3) ? (2 + 2 * l) : (72 + 2 * (l - 3));
    const bool hv   = (l < 6) && (hcol >= 0) && (hcol < WIDTH);

    const u64 M1 = pk2(-1.f, -1.f);

    // UV ring in registers (static slots via full unroll below)
    u64 rUV[11][2];
#pragma unroll
    for (int s = 0; s < 11; s++) { rUV[s][0] = 0; rUV[s][1] = 0; }

    // Q ring in smem (per-thread private slots, compile-time offsets; no sync
    // needed: written and read by the same thread only)
    ulonglong2* qring = (ulonglong2*)(sm + OF_Q) + tid;
    {
        ulonglong2 z2 = make_ulonglong2(0ull, 0ull);
#pragma unroll
        for (int s = 0; s < 11; s++) qring[s * NT] = z2;
    }

    u64 SUV[2] = {0, 0}, SQ2[2] = {0, 0};
    float acc = 0.f;

    // prefetch rows start, start+1 (own pair + halo pair)
    float2 cp0 = {}, ct0 = {}, cp1 = {}, ct1 = {};
    float2 hp0 = {}, ht0 = {}, hp1 = {}, ht1 = {};
    if (start >= 0) {
        cp0 = *(const float2*)(P + (size_t)start * WIDTH + x0g);
        ct0 = *(const float2*)(T + (size_t)start * WIDTH + x0g);
        if (hv) {
            hp0 = *(const float2*)(P + (size_t)start * WIDTH + hcol);
            ht0 = *(const float2*)(T + (size_t)start * WIDTH + hcol);
        }
    }
    if (start + 1 >= 0) {
        cp1 = *(const float2*)(P + (size_t)(start + 1) * WIDTH + x0g);
        ct1 = *(const float2*)(T + (size_t)(start + 1) * WIDTH + x0g);
        if (hv) {
            hp1 = *(const float2*)(P + (size_t)(start + 1) * WIDTH + hcol);
            ht1 = *(const float2*)(T + (size_t)(start + 1) * WIDTH + hcol);
        }
    }

    int kpar = 0;
    for (int y0 = start; y0 < yend; y0 += 22, kpar ^= 1) {
#pragma unroll
        for (int p = 0; p < 11; p++) {
            const int base = y0 + 2 * p;
            if (base < yend) {                      // uniform across block
                const int ph = kpar ^ (p & 1);
                float2* rA = rowbuf + ((ph * 2 + 0) * 8 + w) * WRS;
                float2* rB = rowbuf + ((ph * 2 + 1) * 8 + w) * WRS;
                const bool vA = (base >= 0) && (base < HEIGHT);
                const bool vB = (base + 1 >= 0) && (base + 1 < HEIGHT);

                u64 oA0 = 0, oA1 = 0, oB0 = 0, oB1 = 0;
                // row A: own + halo writes (zeros when invalid)
                {
                    float4 wo = make_float4(0.f, 0.f, 0.f, 0.f);
                    if (vA) {
                        float u0 = cp0.x + ct0.x, v0 = cp0.x - ct0.x;
                        float u1 = cp0.y + ct0.y, v1 = cp0.y - ct0.y;
                        oA0 = pk2(u0, v0); oA1 = pk2(u1, v1);
                        wo = make_float4(u0, v0, u1, v1);
                    }
                    *(float4*)(rA + xb + 8) = wo;
                    if (l < 6) {
                        float4 wh = make_float4(0.f, 0.f, 0.f, 0.f);
                        if (vA && hv)
                            wh = make_float4(hp0.x + ht0.x, hp0.x - ht0.x,
                                             hp0.y + ht0.y, hp0.y - ht0.y);
                        *(float4*)(rA + hbuf) = wh;
                    }
                }
                // row B
                {
                    float4 wo = make_float4(0.f, 0.f, 0.f, 0.f);
                    if (vB) {
                        float u0 = cp1.x + ct1.x, v0 = cp1.x - ct1.x;
                        float u1 = cp1.y + ct1.y, v1 = cp1.y - ct1.y;
                        oB0 = pk2(u0, v0); oB1 = pk2(u1, v1);
                        wo = make_float4(u0, v0, u1, v1);
                    }
                    *(float4*)(rB + xb + 8) = wo;
                    if (l < 6) {
                        float4 wh = make_float4(0.f, 0.f, 0.f, 0.f);
                        if (vB && hv)
                            wh = make_float4(hp1.x + ht1.x, hp1.x - ht1.x,
                                             hp1.y + ht1.y, hp1.y - ht1.y);
                        *(float4*)(rB + hbuf) = wh;
                    }
                }
                // prefetch next row pair (own + halo)
                {
                    int yn0 = base + 2, yn1 = base + 3;
                    if (yn0 >= 0 && yn0 < HEIGHT) {
                        cp0 = *(const float2*)(P + (size_t)yn0 * WIDTH + x0g);
                        ct0 = *(const float2*)(T + (size_t)yn0 * WIDTH + x0g);
                        if (hv) {
                            hp0 = *(const float2*)(P + (size_t)yn0 * WIDTH + hcol);
                            ht0 = *(const float2*)(T + (size_t)yn0 * WIDTH + hcol);
                        }
                    }
                    if (yn1 >= 0 && yn1 < HEIGHT) {
                        cp1 = *(const float2*)(P + (size_t)yn1 * WIDTH + x0g);
                        ct1 = *(const float2*)(T + (size_t)yn1 * WIDTH + x0g);
                        if (hv) {
                            hp1 = *(const float2*)(P + (size_t)yn1 * WIDTH + hcol);
                            ht1 = *(const float2*)(T + (size_t)yn1 * WIDTH + hcol);
                        }
                    }
                }
                __syncwarp();   // warp-private tile visible (no CTA barrier!)

                u64 hUV[2], hQ[2];
                // ---- row A, ring slot (2p)%11 (compile-time constant) ----
                hwin2(rA, xb, oA0, oA1, hUV, hQ);
                {
                    const int sA = (2 * p) % 11;
                    ulonglong2 q = qring[sA * NT];
                    SUV[0] = add2(SUV[0], fma2(rUV[sA][0], M1, hUV[0]));
                    SUV[1] = add2(SUV[1], fma2(rUV[sA][1], M1, hUV[1]));
                    SQ2[0] = add2(SQ2[0], fma2(q.x, M1, hQ[0]));
                    SQ2[1] = add2(SQ2[1], fma2(q.y, M1, hQ[1]));
                    rUV[sA][0] = hUV[0]; rUV[sA][1] = hUV[1];
                    qring[sA * NT] = make_ulonglong2(hQ[0], hQ[1]);
                }
                if (base >= emit0) emit2(SUV, SQ2, acc);

                // ---- row B, ring slot (2p+1)%11 ----
                hwin2(rB, xb, oB0, oB1, hUV, hQ);
                {
                    const int sB = (2 * p + 1) % 11;
                    ulonglong2 q = qring[sB * NT];
                    SUV[0] = add2(SUV[0], fma2(rUV[sB][0], M1, hUV[0]));
                    SUV[1] = add2(SUV[1], fma2(rUV[sB][1], M1, hUV[1]));
                    SQ2[0] = add2(SQ2[0], fma2(q.x, M1, hQ[0]));
                    SQ2[1] = add2(SQ2[1], fma2(q.y, M1, hQ[1]));
                    rUV[sB][0] = hUV[0]; rUV[sB][1] = hUV[1];
                    qring[sB * NT] = make_ulonglong2(hQ[0], hQ[1]);
                }
                if (base + 1 >= emit0 && base + 1 < yend) emit2(SUV, SQ2, acc);
            }
        }
    }

    // deterministic block reduction
    red[tid] = acc;
    __syncthreads();
#pragma unroll
    for (int s = NT / 2; s > 0; s >>= 1) {
        if (tid < s) red[tid] += red[tid + s];
        __syncthreads();
    }
    if (tid == 0) {
        g_partials[bid] = red[0];
        __threadfence();
        unsigned int c = atomicAdd(&g_count, 1);
        s_last = (c == NBLOCKS - 1);
    }
    __syncthreads();
    if (s_last) {
        if (tid < 16) {
            float s = 0.f;
#pragma unroll
            for (int j = 0; j < 3 * NSTRIP; j++)
                s += __ldcg(&g_partials[tid * (3 * NSTRIP) + j]);
            out[tid] = 1.f - s * (1.f / (3.f * 512.f * 512.f));
        }
        if (tid == 0) g_count = 0;   // reset for next graph replay
    }
}

extern "C" void kernel_launch(void* const* d_in, const int* in_sizes, int n_in,
                              void* d_out, int out_size) {
    const float* pred = (const float*)d_in[0];
    const float* targ = (const float*)d_in[1];
    cudaFuncSetAttribute(ssim_main_kernel,
                         cudaFuncAttributeMaxDynamicSharedMemorySize, SMEM_SZ);
    ssim_main_kernel<<<NBLOCKS, NT, SMEM_SZ>>>(pred, targ, (float*)d_out);
}